// round 13
// baseline (speedup 1.0000x reference)
#include <cuda_runtime.h>
#include <cuda_bf16.h>
#include <math.h>
#include <stdint.h>

#define BB   8
#define NN   4096
#define MM   4096
#define KK   64

#define FINF __int_as_float(0x7F800000)

__device__ float g_min_m[BB * NN];
__device__ float g_min_n[BB * MM];
__device__ float g_x2[BB * NN];
__device__ float g_y2[BB * MM];

// Pre-converted, pre-swizzled 16 KB tile images (smem-ready, 128 rows each).
__device__ __align__(16384) unsigned char g_xbf[BB * NN * 128];
__device__ __align__(16384) unsigned char g_ybf[BB * MM * 128];

__device__ __forceinline__ uint32_t s2u(const void* p) {
    uint32_t a;
    asm("{ .reg .u64 t; cvta.to.shared.u64 t, %1; cvt.u32.u64 %0, t; }"
        : "=r"(a) : "l"(p));
    return a;
}

#define SWZ(o) ((o) ^ (((o) >> 3) & 0x70))

// SMEM: A [0,16K), B[ph] at 16K + ph*16K, ph = 0..3.  Total 80 KB.
#define SM_B     16384
#define SMEM_SZ  81920

// ---------------------------------------------------------------------------
// Kernel 1: convert + swizzle-pack + norms + min-init. 16 lanes per row.
// ---------------------------------------------------------------------------
__global__ void prep_kernel(const float* __restrict__ x,
                            const float* __restrict__ y) {
    const int gid = blockIdx.x * blockDim.x + threadIdx.x;
    const int row = gid >> 4, k4 = gid & 15;
    const int R = BB * NN;
    const bool isx = row < R;
    const int r = isx ? row : row - R;

    const float4 v = ((const float4*)((isx ? x : y) + (size_t)r * KK))[k4];
    const uint32_t off = (uint32_t)(r >> 7) * 16384u +
                         SWZ((uint32_t)((r & 127) * 128 + k4 * 8));

    __nv_bfloat162 p01 = __floats2bfloat162_rn(v.x, v.y);
    __nv_bfloat162 p23 = __floats2bfloat162_rn(v.z, v.w);
    uint2 h;
    h.x = *reinterpret_cast<uint32_t*>(&p01);
    h.y = *reinterpret_cast<uint32_t*>(&p23);
    *(uint2*)((isx ? g_xbf : g_ybf) + off) = h;

    float s = v.x * v.x + v.y * v.y + v.z * v.z + v.w * v.w;
    s += __shfl_xor_sync(~0u, s, 1);
    s += __shfl_xor_sync(~0u, s, 2);
    s += __shfl_xor_sync(~0u, s, 4);
    s += __shfl_xor_sync(~0u, s, 8);
    if (k4 == 0) {
        if (isx) { g_x2[r] = s; g_min_m[r] = FINF; }
        else     { g_y2[r] = s; g_min_n[r] = FINF; }
    }
}

__device__ __forceinline__ void mma16816(float* c, const uint32_t* a,
                                         const uint32_t* b) {
    asm volatile(
        "mma.sync.aligned.m16n8k16.row.col.f32.bf16.bf16.f32 "
        "{%0,%1,%2,%3}, {%4,%5,%6,%7}, {%8,%9}, {%0,%1,%2,%3};"
        : "+f"(c[0]), "+f"(c[1]), "+f"(c[2]), "+f"(c[3])
        : "r"(a[0]), "r"(a[1]), "r"(a[2]), "r"(a[3]), "r"(b[0]), "r"(b[1]));
}

__device__ __forceinline__ void cp16(uint32_t dst, const void* src) {
    asm volatile("cp.async.cg.shared.global [%0], [%1], 16;"
                 :: "r"(dst), "l"(src) : "memory");
}

// ---------------------------------------------------------------------------
// Kernel 2: per CTA: one A tile (128 n-rows) x four B tiles (4 x 128 m-rows).
// 4 compute phases against the same A; row-min carried across phases.
// 8 warps: wn = w>>2 (64-row band), wc = w&3 (32-col band).
// ---------------------------------------------------------------------------
extern __shared__ char smem[];

__global__ void __launch_bounds__(256, 2)
tile_hmma_kernel() {
    const uint32_t sb = s2u(smem);
    const int t = threadIdx.x, lane = t & 31, w = t >> 5;
    const int wn = w >> 2;
    const int wc = w & 3;
    const int b = blockIdx.z, n0 = blockIdx.y * 128;
    const int mg = blockIdx.x * 4;               // first of 4 m-tiles

    // Prefetch: group 1 = A + B0, group 2 = B1..B3.
    {
        const uint32_t o = (uint32_t)t * 16;
        const unsigned char* asrc = g_xbf + (size_t)(b * 32 + blockIdx.y) * 16384;
        const unsigned char* bsrc = g_ybf + (size_t)(b * 32 + mg) * 16384;
#pragma unroll
        for (int i = 0; i < 4; i++) {
            cp16(sb + o + i * 4096, asrc + o + i * 4096);
            cp16(sb + SM_B + o + i * 4096, bsrc + o + i * 4096);
        }
        asm volatile("cp.async.commit_group;" ::: "memory");
#pragma unroll
        for (int ph = 1; ph < 4; ph++) {
            const unsigned char* s2 = bsrc + (size_t)ph * 16384;
            const uint32_t d2 = sb + SM_B + ph * 16384;
#pragma unroll
            for (int i = 0; i < 4; i++) cp16(d2 + o + i * 4096, s2 + o + i * 4096);
        }
        asm volatile("cp.async.commit_group;" ::: "memory");
    }

    // Per-lane ldmatrix base offsets (bytes, pre-swizzle).
    const int tq = lane >> 3, tr = lane & 7;
    uint32_t aOff[4], bOff[4];
#pragma unroll
    for (int mt = 0; mt < 4; mt++)
        aOff[mt] = (uint32_t)((wn * 64 + mt * 16 + (tq & 1) * 8 + tr) * 128 +
                              (tq >> 1) * 16);
    const int l16 = lane & 15;
#pragma unroll
    for (int nt = 0; nt < 4; nt++)
        bOff[nt] = (uint32_t)((wc * 32 + nt * 8 + (l16 & 7)) * 128 +
                              (l16 >> 3) * 16);

    // Row scalars: fixed for all phases.
    float x2r[8];
#pragma unroll
    for (int mt = 0; mt < 4; mt++)
#pragma unroll
        for (int s = 0; s < 2; s++)
            x2r[mt * 2 + s] = __ldg(
                &g_x2[b * NN + n0 + wn * 64 + mt * 16 + (lane >> 2) + s * 8]);

    float rowAll[8];
#pragma unroll
    for (int i = 0; i < 8; i++) rowAll[i] = FINF;

    asm volatile("cp.async.wait_group 1;" ::: "memory");
    __syncthreads();

#pragma unroll 1
    for (int ph = 0; ph < 4; ph++) {
        if (ph == 1) {
            asm volatile("cp.async.wait_group 0;" ::: "memory");
            __syncthreads();
        }
        const uint32_t bbase = sb + SM_B + ph * 16384;
        const int m0 = (mg + ph) * 128;

        float acc[4][4][4];
#pragma unroll
        for (int i = 0; i < 4; i++)
#pragma unroll
            for (int j = 0; j < 4; j++)
#pragma unroll
                for (int e = 0; e < 4; e++) acc[i][j][e] = 0.f;

#pragma unroll
        for (int kk = 0; kk < 4; kk++) {
            const uint32_t kcol = kk * 32;
            uint32_t a[4][4], bf[4][2];
#pragma unroll
            for (int mt = 0; mt < 4; mt++) {
                uint32_t addr = sb + SWZ(aOff[mt] + kcol);
                asm volatile("ldmatrix.sync.aligned.m8n8.x4.shared.b16 "
                             "{%0,%1,%2,%3}, [%4];"
                             : "=r"(a[mt][0]), "=r"(a[mt][1]),
                               "=r"(a[mt][2]), "=r"(a[mt][3]) : "r"(addr));
            }
#pragma unroll
            for (int nt = 0; nt < 4; nt++) {
                uint32_t addr = bbase + SWZ(bOff[nt] + kcol);
                asm volatile("ldmatrix.sync.aligned.m8n8.x2.shared.b16 "
                             "{%0,%1}, [%2];"
                             : "=r"(bf[nt][0]), "=r"(bf[nt][1]) : "r"(addr));
            }
#pragma unroll
            for (int mt = 0; mt < 4; mt++)
#pragma unroll
                for (int nt = 0; nt < 4; nt++)
                    mma16816(acc[mt][nt], a[mt], bf[nt]);
        }

        // Phase epilogue. Fragment e -> row l/4+(e>>1)*8, col 2*(l%4)+(e&1)
        float y2c[8];
#pragma unroll
        for (int nt = 0; nt < 4; nt++)
#pragma unroll
            for (int e = 0; e < 2; e++)
                y2c[nt * 2 + e] = __ldg(
                    &g_y2[b * MM + m0 + wc * 32 + nt * 8 + 2 * (lane & 3) + e]);

        float colmin[8];
#pragma unroll
        for (int i = 0; i < 8; i++) colmin[i] = FINF;

#pragma unroll
        for (int mt = 0; mt < 4; mt++)
#pragma unroll
            for (int nt = 0; nt < 4; nt++)
#pragma unroll
                for (int e = 0; e < 4; e++) {
                    const int ri = mt * 2 + (e >> 1), cj = nt * 2 + (e & 1);
                    float v = -2.f * acc[mt][nt][e];
                    rowAll[ri] = fminf(rowAll[ri], v + y2c[cj]);
                    colmin[cj] = fminf(colmin[cj], v + x2r[ri]);
                }

#pragma unroll
        for (int off = 4; off <= 16; off <<= 1)
#pragma unroll
            for (int i = 0; i < 8; i++)
                colmin[i] = fminf(colmin[i],
                                  __shfl_xor_sync(~0u, colmin[i], off));

        if (lane < 4) {
#pragma unroll
            for (int nt = 0; nt < 4; nt++)
#pragma unroll
                for (int e = 0; e < 2; e++) {
                    int col = wc * 32 + nt * 8 + 2 * lane + e;
                    float v = fmaxf(colmin[nt * 2 + e] + y2c[nt * 2 + e], 0.f);
                    atomicMin((int*)&g_min_n[b * MM + m0 + col],
                              __float_as_int(v));
                }
        }
    }

    // Row mins once per CTA.
#pragma unroll
    for (int off = 1; off <= 2; off <<= 1)
#pragma unroll
        for (int i = 0; i < 8; i++)
            rowAll[i] = fminf(rowAll[i], __shfl_xor_sync(~0u, rowAll[i], off));
    if ((lane & 3) == 0) {
#pragma unroll
        for (int mt = 0; mt < 4; mt++)
#pragma unroll
            for (int s = 0; s < 2; s++) {
                int row = wn * 64 + mt * 16 + (lane >> 2) + s * 8;
                float v = fmaxf(rowAll[mt * 2 + s] + x2r[mt * 2 + s], 0.f);
                atomicMin((int*)&g_min_m[b * NN + n0 + row], __float_as_int(v));
            }
    }
}

// ---------------------------------------------------------------------------
// Kernel 3: loss = sum(sqrt(mins)) / (B * 4096)
// ---------------------------------------------------------------------------
__global__ void reduce_kernel(float* __restrict__ out) {
    __shared__ float ssum[1024];
    int t = threadIdx.x;
    float s = 0.f;
    for (int i = t; i < BB * NN; i += 1024)
        s += sqrtf(g_min_m[i]) + sqrtf(g_min_n[i]);
    ssum[t] = s;
    __syncthreads();
#pragma unroll
    for (int off = 512; off > 0; off >>= 1) {
        if (t < off) ssum[t] += ssum[t + off];
        __syncthreads();
    }
    if (t == 0) out[0] = ssum[0] * (1.0f / (BB * NN));
}

// ---------------------------------------------------------------------------
extern "C" void kernel_launch(void* const* d_in, const int* in_sizes, int n_in,
                              void* d_out, int out_size) {
    const float* x = (const float*)d_in[0];
    const float* y = (const float*)d_in[1];
    float* out = (float*)d_out;

    cudaFuncSetAttribute(tile_hmma_kernel,
                         cudaFuncAttributeMaxDynamicSharedMemorySize, SMEM_SZ);

    prep_kernel<<<(2 * BB * NN * 16) / 256, 256>>>(x, y);

    dim3 grid(MM / 512, NN / 128, BB);   // 8 x 32 x 8 = 2048 CTAs
    tile_hmma_kernel<<<grid, 256, SMEM_SZ>>>();

    reduce_kernel<<<1, 1024>>>(out);
}

// round 14
// speedup vs baseline: 1.7134x; 1.7134x over previous
#include <cuda_runtime.h>
#include <cuda_bf16.h>
#include <math.h>
#include <stdint.h>

#define BB   8
#define NN   4096
#define MM   4096
#define KK   64

#define FINF __int_as_float(0x7F800000)

__device__ float g_min_m[BB * NN];
__device__ float g_min_n[BB * MM];
__device__ float g_x2[BB * NN];
__device__ float g_y2[BB * MM];

// Pre-converted, pre-swizzled 16 KB tile images (smem-ready, 128 rows each).
__device__ __align__(16384) unsigned char g_xbf[BB * NN * 128];
__device__ __align__(16384) unsigned char g_ybf[BB * MM * 128];

__device__ __forceinline__ uint32_t s2u(const void* p) {
    uint32_t a;
    asm("{ .reg .u64 t; cvta.to.shared.u64 t, %1; cvt.u32.u64 %0, t; }"
        : "=r"(a) : "l"(p));
    return a;
}

#define SWZ(o) ((o) ^ (((o) >> 3) & 0x70))

// SMEM: A [0,16K), B0 [16K,32K), B1 [32K,48K)
#define SM_B     16384
#define SMEM_SZ  49152

// ---------------------------------------------------------------------------
// Kernel 1: convert + swizzle-pack + norms + min-init. 16 lanes per row.
// Thread 0 also zeroes out[0] for the atomic final reduction.
// ---------------------------------------------------------------------------
__global__ void prep_kernel(const float* __restrict__ x,
                            const float* __restrict__ y,
                            float* __restrict__ out) {
    const int gid = blockIdx.x * blockDim.x + threadIdx.x;
    if (gid == 0) out[0] = 0.f;
    const int row = gid >> 4, k4 = gid & 15;
    const int R = BB * NN;
    const bool isx = row < R;
    const int r = isx ? row : row - R;

    const float4 v = ((const float4*)((isx ? x : y) + (size_t)r * KK))[k4];
    const uint32_t off = (uint32_t)(r >> 7) * 16384u +
                         SWZ((uint32_t)((r & 127) * 128 + k4 * 8));

    __nv_bfloat162 p01 = __floats2bfloat162_rn(v.x, v.y);
    __nv_bfloat162 p23 = __floats2bfloat162_rn(v.z, v.w);
    uint2 h;
    h.x = *reinterpret_cast<uint32_t*>(&p01);
    h.y = *reinterpret_cast<uint32_t*>(&p23);
    *(uint2*)((isx ? g_xbf : g_ybf) + off) = h;

    float s = v.x * v.x + v.y * v.y + v.z * v.z + v.w * v.w;
    s += __shfl_xor_sync(~0u, s, 1);
    s += __shfl_xor_sync(~0u, s, 2);
    s += __shfl_xor_sync(~0u, s, 4);
    s += __shfl_xor_sync(~0u, s, 8);
    if (k4 == 0) {
        if (isx) { g_x2[r] = s; g_min_m[r] = FINF; }
        else     { g_y2[r] = s; g_min_n[r] = FINF; }
    }
}

__device__ __forceinline__ void mma16816(float* c, const uint32_t* a,
                                         const uint32_t* b) {
    asm volatile(
        "mma.sync.aligned.m16n8k16.row.col.f32.bf16.bf16.f32 "
        "{%0,%1,%2,%3}, {%4,%5,%6,%7}, {%8,%9}, {%0,%1,%2,%3};"
        : "+f"(c[0]), "+f"(c[1]), "+f"(c[2]), "+f"(c[3])
        : "r"(a[0]), "r"(a[1]), "r"(a[2]), "r"(a[3]), "r"(b[0]), "r"(b[1]));
}

__device__ __forceinline__ void cp16(uint32_t dst, const void* src) {
    asm volatile("cp.async.cg.shared.global [%0], [%1], 16;"
                 :: "r"(dst), "l"(src) : "memory");
}

// ---------------------------------------------------------------------------
// Kernel 2: per CTA: one A tile (128 n-rows) x two B tiles (2 x 128 m-rows).
// Nothing carried across phases: register budget identical to the 1-tile
// version. 8 warps: wn = w>>2 (64-row band), wc = w&3 (32-col band).
// ---------------------------------------------------------------------------
extern __shared__ char smem[];

__global__ void __launch_bounds__(256, 2)
tile_hmma_kernel() {
    const uint32_t sb = s2u(smem);
    const int t = threadIdx.x, lane = t & 31, w = t >> 5;
    const int wn = w >> 2;
    const int wc = w & 3;
    const int b = blockIdx.z, n0 = blockIdx.y * 128;
    const int mg = blockIdx.x * 2;               // first of 2 m-tiles

    // Prefetch: group 1 = A + B0, group 2 = B1.
    {
        const uint32_t o = (uint32_t)t * 16;
        const unsigned char* asrc = g_xbf + (size_t)(b * 32 + blockIdx.y) * 16384;
        const unsigned char* bsrc = g_ybf + (size_t)(b * 32 + mg) * 16384;
#pragma unroll
        for (int i = 0; i < 4; i++) {
            cp16(sb + o + i * 4096, asrc + o + i * 4096);
            cp16(sb + SM_B + o + i * 4096, bsrc + o + i * 4096);
        }
        asm volatile("cp.async.commit_group;" ::: "memory");
#pragma unroll
        for (int i = 0; i < 4; i++)
            cp16(sb + SM_B + 16384 + o + i * 4096, bsrc + 16384 + o + i * 4096);
        asm volatile("cp.async.commit_group;" ::: "memory");
    }

    // Per-lane ldmatrix base offsets (bytes, pre-swizzle).
    const int tq = lane >> 3, tr = lane & 7;
    uint32_t aOff[4];
#pragma unroll
    for (int mt = 0; mt < 4; mt++)
        aOff[mt] = (uint32_t)((wn * 64 + mt * 16 + (tq & 1) * 8 + tr) * 128 +
                              (tq >> 1) * 16);
    // B x4 fused: lane group g = lane>>3 -> matrix (nt_pair: g>>1, khalf: g&1).
    uint32_t bOff[2];
#pragma unroll
    for (int np = 0; np < 2; np++)
        bOff[np] = (uint32_t)((wc * 32 + (np * 2 + (tq >> 1)) * 8 + tr) * 128 +
                              (tq & 1) * 16);

    asm volatile("cp.async.wait_group 1;" ::: "memory");
    __syncthreads();

#pragma unroll 1
    for (int ph = 0; ph < 2; ph++) {
        if (ph == 1) {
            asm volatile("cp.async.wait_group 0;" ::: "memory");
            __syncthreads();
        }
        const uint32_t bbase = sb + SM_B + ph * 16384;
        const int m0 = (mg + ph) * 128;

        float acc[4][4][4];
#pragma unroll
        for (int i = 0; i < 4; i++)
#pragma unroll
            for (int j = 0; j < 4; j++)
#pragma unroll
                for (int e = 0; e < 4; e++) acc[i][j][e] = 0.f;

#pragma unroll
        for (int kk = 0; kk < 4; kk++) {
            const uint32_t kcol = kk * 32;
            uint32_t a[4][4], bf[4][2];
#pragma unroll
            for (int mt = 0; mt < 4; mt++) {
                uint32_t addr = sb + SWZ(aOff[mt] + kcol);
                asm volatile("ldmatrix.sync.aligned.m8n8.x4.shared.b16 "
                             "{%0,%1,%2,%3}, [%4];"
                             : "=r"(a[mt][0]), "=r"(a[mt][1]),
                               "=r"(a[mt][2]), "=r"(a[mt][3]) : "r"(addr));
            }
            // Two fused x4 loads cover four n-tiles (k0/k8 halves interleaved).
#pragma unroll
            for (int np = 0; np < 2; np++) {
                uint32_t addr = bbase + SWZ(bOff[np] + kcol);
                asm volatile("ldmatrix.sync.aligned.m8n8.x4.shared.b16 "
                             "{%0,%1,%2,%3}, [%4];"
                             : "=r"(bf[np * 2][0]), "=r"(bf[np * 2][1]),
                               "=r"(bf[np * 2 + 1][0]), "=r"(bf[np * 2 + 1][1])
                             : "r"(addr));
            }
#pragma unroll
            for (int mt = 0; mt < 4; mt++)
#pragma unroll
                for (int nt = 0; nt < 4; nt++)
                    mma16816(acc[mt][nt], a[mt], bf[nt]);
        }

        // Phase epilogue. Fragment e -> row l/4+(e>>1)*8, col 2*(l%4)+(e&1)
        float x2r[8], y2c[8];
#pragma unroll
        for (int mt = 0; mt < 4; mt++)
#pragma unroll
            for (int s = 0; s < 2; s++)
                x2r[mt * 2 + s] = __ldg(
                    &g_x2[b * NN + n0 + wn * 64 + mt * 16 + (lane >> 2) + s * 8]);
#pragma unroll
        for (int nt = 0; nt < 4; nt++)
#pragma unroll
            for (int e = 0; e < 2; e++)
                y2c[nt * 2 + e] = __ldg(
                    &g_y2[b * MM + m0 + wc * 32 + nt * 8 + 2 * (lane & 3) + e]);

        float rowmin[8], colmin[8];
#pragma unroll
        for (int i = 0; i < 8; i++) { rowmin[i] = FINF; colmin[i] = FINF; }

#pragma unroll
        for (int mt = 0; mt < 4; mt++)
#pragma unroll
            for (int nt = 0; nt < 4; nt++)
#pragma unroll
                for (int e = 0; e < 4; e++) {
                    const int ri = mt * 2 + (e >> 1), cj = nt * 2 + (e & 1);
                    float v = -2.f * acc[mt][nt][e];
                    rowmin[ri] = fminf(rowmin[ri], v + y2c[cj]);
                    colmin[cj] = fminf(colmin[cj], v + x2r[ri]);
                }

#pragma unroll
        for (int off = 1; off <= 2; off <<= 1)
#pragma unroll
            for (int i = 0; i < 8; i++)
                rowmin[i] = fminf(rowmin[i],
                                  __shfl_xor_sync(~0u, rowmin[i], off));
#pragma unroll
        for (int off = 4; off <= 16; off <<= 1)
#pragma unroll
            for (int i = 0; i < 8; i++)
                colmin[i] = fminf(colmin[i],
                                  __shfl_xor_sync(~0u, colmin[i], off));

        if ((lane & 3) == 0) {
#pragma unroll
            for (int mt = 0; mt < 4; mt++)
#pragma unroll
                for (int s = 0; s < 2; s++) {
                    int row = wn * 64 + mt * 16 + (lane >> 2) + s * 8;
                    float v = fmaxf(rowmin[mt * 2 + s] + x2r[mt * 2 + s], 0.f);
                    atomicMin((int*)&g_min_m[b * NN + n0 + row],
                              __float_as_int(v));
                }
        }
        if (lane < 4) {
#pragma unroll
            for (int nt = 0; nt < 4; nt++)
#pragma unroll
                for (int e = 0; e < 2; e++) {
                    int col = wc * 32 + nt * 8 + 2 * lane + e;
                    float v = fmaxf(colmin[nt * 2 + e] + y2c[nt * 2 + e], 0.f);
                    atomicMin((int*)&g_min_n[b * MM + m0 + col],
                              __float_as_int(v));
                }
        }
    }
}

// ---------------------------------------------------------------------------
// Kernel 3: parallel loss reduction: 16 blocks, block-sum + atomicAdd.
// ---------------------------------------------------------------------------
__global__ void reduce_kernel(float* __restrict__ out) {
    __shared__ float ssum[1024];
    const int t = threadIdx.x;
    const int base = blockIdx.x * (2 * BB * NN / 16);
    float s = 0.f;
    for (int i = t; i < BB * NN / 16; i += 1024) {
        int idx = base + i;   // first half covers g_min_m, second g_min_n
        s += (idx < BB * NN) ? sqrtf(g_min_m[idx])
                             : sqrtf(g_min_n[idx - BB * NN]);
    }
    // second stripe of this block's range
    for (int i = t; i < BB * NN / 16; i += 1024) {
        int idx = base + BB * NN / 16 + i;
        s += (idx < BB * NN) ? sqrtf(g_min_m[idx])
                             : sqrtf(g_min_n[idx - BB * NN]);
    }
    ssum[t] = s;
    __syncthreads();
#pragma unroll
    for (int off = 512; off > 0; off >>= 1) {
        if (t < off) ssum[t] += ssum[t + off];
        __syncthreads();
    }
    if (t == 0) atomicAdd(out, ssum[0] * (1.0f / (BB * NN)));
}

// ---------------------------------------------------------------------------
extern "C" void kernel_launch(void* const* d_in, const int* in_sizes, int n_in,
                              void* d_out, int out_size) {
    const float* x = (const float*)d_in[0];
    const float* y = (const float*)d_in[1];
    float* out = (float*)d_out;

    cudaFuncSetAttribute(tile_hmma_kernel,
                         cudaFuncAttributeMaxDynamicSharedMemorySize, SMEM_SZ);

    prep_kernel<<<(2 * BB * NN * 16) / 256, 256>>>(x, y, out);

    dim3 grid(MM / 256, NN / 128, BB);   // 16 x 32 x 8 = 4096 CTAs
    tile_hmma_kernel<<<grid, 256, SMEM_SZ>>>();

    reduce_kernel<<<16, 1024>>>(out);
}

// round 16
// speedup vs baseline: 1.7532x; 1.0232x over previous
#include <cuda_runtime.h>
#include <cuda_bf16.h>
#include <math.h>
#include <stdint.h>

#define BB   8
#define NN   4096
#define MM   4096
#define KK   64

#define FINF __int_as_float(0x7F800000)

__device__ float g_min_m[BB * NN];
__device__ float g_min_n[BB * MM];
__device__ float g_x2[BB * NN];
__device__ float g_y2[BB * MM];

// Pre-converted, pre-swizzled 16 KB tile images (smem-ready, 128 rows each).
__device__ __align__(16384) unsigned char g_xbf[BB * NN * 128];
__device__ __align__(16384) unsigned char g_ybf[BB * MM * 128];

__device__ __forceinline__ uint32_t s2u(const void* p) {
    uint32_t a;
    asm("{ .reg .u64 t; cvta.to.shared.u64 t, %1; cvt.u32.u64 %0, t; }"
        : "=r"(a) : "l"(p));
    return a;
}

#define SWZ(o) ((o) ^ (((o) >> 3) & 0x70))

// SMEM: A [0,16K), B[ph] at 16K + ph*16K, ph = 0..3.  Total 80 KB.
#define SM_B     16384
#define SMEM_SZ  81920

// ---------------------------------------------------------------------------
// Kernel 1: convert + swizzle-pack + norms + min-init. 16 lanes per row.
// Thread 0 also zeroes out[0] for the atomic final reduction.
// ---------------------------------------------------------------------------
__global__ void prep_kernel(const float* __restrict__ x,
                            const float* __restrict__ y,
                            float* __restrict__ out) {
    const int gid = blockIdx.x * blockDim.x + threadIdx.x;
    if (gid == 0) out[0] = 0.f;
    const int row = gid >> 4, k4 = gid & 15;
    const int R = BB * NN;
    const bool isx = row < R;
    const int r = isx ? row : row - R;

    const float4 v = ((const float4*)((isx ? x : y) + (size_t)r * KK))[k4];
    const uint32_t off = (uint32_t)(r >> 7) * 16384u +
                         SWZ((uint32_t)((r & 127) * 128 + k4 * 8));

    __nv_bfloat162 p01 = __floats2bfloat162_rn(v.x, v.y);
    __nv_bfloat162 p23 = __floats2bfloat162_rn(v.z, v.w);
    uint2 h;
    h.x = *reinterpret_cast<uint32_t*>(&p01);
    h.y = *reinterpret_cast<uint32_t*>(&p23);
    *(uint2*)((isx ? g_xbf : g_ybf) + off) = h;

    float s = v.x * v.x + v.y * v.y + v.z * v.z + v.w * v.w;
    s += __shfl_xor_sync(~0u, s, 1);
    s += __shfl_xor_sync(~0u, s, 2);
    s += __shfl_xor_sync(~0u, s, 4);
    s += __shfl_xor_sync(~0u, s, 8);
    if (k4 == 0) {
        if (isx) { g_x2[r] = s; g_min_m[r] = FINF; }
        else     { g_y2[r] = s; g_min_n[r] = FINF; }
    }
}

__device__ __forceinline__ void mma16816(float* c, const uint32_t* a,
                                         const uint32_t* b) {
    asm volatile(
        "mma.sync.aligned.m16n8k16.row.col.f32.bf16.bf16.f32 "
        "{%0,%1,%2,%3}, {%4,%5,%6,%7}, {%8,%9}, {%0,%1,%2,%3};"
        : "+f"(c[0]), "+f"(c[1]), "+f"(c[2]), "+f"(c[3])
        : "r"(a[0]), "r"(a[1]), "r"(a[2]), "r"(a[3]), "r"(b[0]), "r"(b[1]));
}

__device__ __forceinline__ void cp16(uint32_t dst, const void* src) {
    asm volatile("cp.async.cg.shared.global [%0], [%1], 16;"
                 :: "r"(dst), "l"(src) : "memory");
}

// ---------------------------------------------------------------------------
// Kernel 2: per CTA: one A tile (128 n-rows) x four B tiles (4 x 128 m-rows).
// Strictly per-phase register scope (the R12 failure was carried state).
// Progressive cp.async groups: {A+B0}, {B1}, {B2}, {B3}.
// 8 warps: wn = w>>2 (64-row band), wc = w&3 (32-col band).
// ---------------------------------------------------------------------------
extern __shared__ char smem[];

__global__ void __launch_bounds__(256, 2)
tile_hmma_kernel() {
    const uint32_t sb = s2u(smem);
    const int t = threadIdx.x, lane = t & 31, w = t >> 5;
    const int wn = w >> 2;
    const int wc = w & 3;
    const int b = blockIdx.z, n0 = blockIdx.y * 128;
    const int mg = blockIdx.x * 4;               // first of 4 m-tiles

    // Prefetch: group0 = A + B0, then one group per remaining B tile.
    {
        const uint32_t o = (uint32_t)t * 16;
        const unsigned char* asrc = g_xbf + (size_t)(b * 32 + blockIdx.y) * 16384;
        const unsigned char* bsrc = g_ybf + (size_t)(b * 32 + mg) * 16384;
#pragma unroll
        for (int i = 0; i < 4; i++) {
            cp16(sb + o + i * 4096, asrc + o + i * 4096);
            cp16(sb + SM_B + o + i * 4096, bsrc + o + i * 4096);
        }
        asm volatile("cp.async.commit_group;" ::: "memory");
#pragma unroll
        for (int ph = 1; ph < 4; ph++) {
            const unsigned char* s2 = bsrc + (size_t)ph * 16384;
            const uint32_t d2 = sb + SM_B + ph * 16384;
#pragma unroll
            for (int i = 0; i < 4; i++)
                cp16(d2 + o + i * 4096, s2 + o + i * 4096);
            asm volatile("cp.async.commit_group;" ::: "memory");
        }
    }

    // Per-lane ldmatrix base offsets (bytes, pre-swizzle).
    const int tq = lane >> 3, tr = lane & 7;
    uint32_t aOff[4];
#pragma unroll
    for (int mt = 0; mt < 4; mt++)
        aOff[mt] = (uint32_t)((wn * 64 + mt * 16 + (tq & 1) * 8 + tr) * 128 +
                              (tq >> 1) * 16);
    // B x4 fused: lane group g = lane>>3 -> matrix (nt_pair: g>>1, khalf: g&1).
    uint32_t bOff[2];
#pragma unroll
    for (int np = 0; np < 2; np++)
        bOff[np] = (uint32_t)((wc * 32 + (np * 2 + (tq >> 1)) * 8 + tr) * 128 +
                              (tq & 1) * 16);

    asm volatile("cp.async.wait_group 3;" ::: "memory");
    __syncthreads();

#pragma unroll 1
    for (int ph = 0; ph < 4; ph++) {
        if (ph == 1) {
            asm volatile("cp.async.wait_group 2;" ::: "memory");
            __syncthreads();
        } else if (ph == 2) {
            asm volatile("cp.async.wait_group 1;" ::: "memory");
            __syncthreads();
        } else if (ph == 3) {
            asm volatile("cp.async.wait_group 0;" ::: "memory");
            __syncthreads();
        }
        const uint32_t bbase = sb + SM_B + ph * 16384;
        const int m0 = (mg + ph) * 128;

        float acc[4][4][4];
#pragma unroll
        for (int i = 0; i < 4; i++)
#pragma unroll
            for (int j = 0; j < 4; j++)
#pragma unroll
                for (int e = 0; e < 4; e++) acc[i][j][e] = 0.f;

#pragma unroll
        for (int kk = 0; kk < 4; kk++) {
            const uint32_t kcol = kk * 32;
            uint32_t a[4][4], bf[4][2];
#pragma unroll
            for (int mt = 0; mt < 4; mt++) {
                uint32_t addr = sb + SWZ(aOff[mt] + kcol);
                asm volatile("ldmatrix.sync.aligned.m8n8.x4.shared.b16 "
                             "{%0,%1,%2,%3}, [%4];"
                             : "=r"(a[mt][0]), "=r"(a[mt][1]),
                               "=r"(a[mt][2]), "=r"(a[mt][3]) : "r"(addr));
            }
#pragma unroll
            for (int np = 0; np < 2; np++) {
                uint32_t addr = bbase + SWZ(bOff[np] + kcol);
                asm volatile("ldmatrix.sync.aligned.m8n8.x4.shared.b16 "
                             "{%0,%1,%2,%3}, [%4];"
                             : "=r"(bf[np * 2][0]), "=r"(bf[np * 2][1]),
                               "=r"(bf[np * 2 + 1][0]), "=r"(bf[np * 2 + 1][1])
                             : "r"(addr));
            }
#pragma unroll
            for (int mt = 0; mt < 4; mt++)
#pragma unroll
                for (int nt = 0; nt < 4; nt++)
                    mma16816(acc[mt][nt], a[mt], bf[nt]);
        }

        // Phase epilogue (fully re-scoped each phase).
        float x2r[8], y2c[8];
#pragma unroll
        for (int mt = 0; mt < 4; mt++)
#pragma unroll
            for (int s = 0; s < 2; s++)
                x2r[mt * 2 + s] = __ldg(
                    &g_x2[b * NN + n0 + wn * 64 + mt * 16 + (lane >> 2) + s * 8]);
#pragma unroll
        for (int nt = 0; nt < 4; nt++)
#pragma unroll
            for (int e = 0; e < 2; e++)
                y2c[nt * 2 + e] = __ldg(
                    &g_y2[b * MM + m0 + wc * 32 + nt * 8 + 2 * (lane & 3) + e]);

        float rowmin[8], colmin[8];
#pragma unroll
        for (int i = 0; i < 8; i++) { rowmin[i] = FINF; colmin[i] = FINF; }

#pragma unroll
        for (int mt = 0; mt < 4; mt++)
#pragma unroll
            for (int nt = 0; nt < 4; nt++)
#pragma unroll
                for (int e = 0; e < 4; e++) {
                    const int ri = mt * 2 + (e >> 1), cj = nt * 2 + (e & 1);
                    float v = -2.f * acc[mt][nt][e];
                    rowmin[ri] = fminf(rowmin[ri], v + y2c[cj]);
                    colmin[cj] = fminf(colmin[cj], v + x2r[ri]);
                }

#pragma unroll
        for (int off = 1; off <= 2; off <<= 1)
#pragma unroll
            for (int i = 0; i < 8; i++)
                rowmin[i] = fminf(rowmin[i],
                                  __shfl_xor_sync(~0u, rowmin[i], off));
#pragma unroll
        for (int off = 4; off <= 16; off <<= 1)
#pragma unroll
            for (int i = 0; i < 8; i++)
                colmin[i] = fminf(colmin[i],
                                  __shfl_xor_sync(~0u, colmin[i], off));

        if ((lane & 3) == 0) {
#pragma unroll
            for (int mt = 0; mt < 4; mt++)
#pragma unroll
                for (int s = 0; s < 2; s++) {
                    int row = wn * 64 + mt * 16 + (lane >> 2) + s * 8;
                    float v = fmaxf(rowmin[mt * 2 + s] + x2r[mt * 2 + s], 0.f);
                    atomicMin((int*)&g_min_m[b * NN + n0 + row],
                              __float_as_int(v));
                }
        }
        if (lane < 4) {
#pragma unroll
            for (int nt = 0; nt < 4; nt++)
#pragma unroll
                for (int e = 0; e < 2; e++) {
                    int col = wc * 32 + nt * 8 + 2 * lane + e;
                    float v = fmaxf(colmin[nt * 2 + e] + y2c[nt * 2 + e], 0.f);
                    atomicMin((int*)&g_min_n[b * MM + m0 + col],
                              __float_as_int(v));
                }
        }
    }
}

// ---------------------------------------------------------------------------
// Kernel 3: parallel loss reduction: 16 blocks, block-sum + atomicAdd.
// ---------------------------------------------------------------------------
__global__ void reduce_kernel(float* __restrict__ out) {
    __shared__ float ssum[1024];
    const int t = threadIdx.x;
    const int base = blockIdx.x * (2 * BB * NN / 16);
    float s = 0.f;
    for (int i = t; i < 2 * BB * NN / 16; i += 1024) {
        int idx = base + i;
        s += (idx < BB * NN) ? sqrtf(g_min_m[idx])
                             : sqrtf(g_min_n[idx - BB * NN]);
    }
    ssum[t] = s;
    __syncthreads();
#pragma unroll
    for (int off = 512; off > 0; off >>= 1) {
        if (t < off) ssum[t] += ssum[t + off];
        __syncthreads();
    }
    if (t == 0) atomicAdd(out, ssum[0] * (1.0f / (BB * NN)));
}

// ---------------------------------------------------------------------------
extern "C" void kernel_launch(void* const* d_in, const int* in_sizes, int n_in,
                              void* d_out, int out_size) {
    const float* x = (const float*)d_in[0];
    const float* y = (const float*)d_in[1];
    float* out = (float*)d_out;

    cudaFuncSetAttribute(tile_hmma_kernel,
                         cudaFuncAttributeMaxDynamicSharedMemorySize, SMEM_SZ);

    prep_kernel<<<(2 * BB * NN * 16) / 256, 256>>>(x, y, out);

    dim3 grid(MM / 512, NN / 128, BB);   // 8 x 32 x 8 = 2048 CTAs
    tile_hmma_kernel<<<grid, 256, SMEM_SZ>>>();

    reduce_kernel<<<16, 1024>>>(out);
}